// round 14
// baseline (speedup 1.0000x reference)
#include <cuda_runtime.h>
#include <cstdint>
#include <math.h>

// Problem constants
#define B_   4
#define H_   8
#define N_   8192
#define DH_  64
#define M_   256
#define L_   32
#define BH_  32

// ---------------- scratch (device globals; no allocation anywhere) ----------------
__device__ float gQ[16777216];     // [BH,N,DH] (pre-scaled, tf32-rounded)
__device__ float gK[16777216];
__device__ float gV[16777216];
__device__ float gQL[524288];      // [BH,M,DH]
__device__ float gKL[524288];
__device__ float gA2[2097152];     // [BH,M,M] softmaxed (tf32-rounded)
__device__ float gZ [2097152];
__device__ float gZT[2097152];
__device__ float gZ2[2097152];
__device__ float gZ2T[2097152];
__device__ float gX [2097152];
__device__ float gT1[2097152];     // U1T / U3T
__device__ float gT2[2097152];     // U2T
__device__ float gA3V[524288];
__device__ float gW [524288];
__device__ float gOH[16777216];
__device__ float gCAT[16777216];   // conv output
__device__ float gWqkvT[786432];   // [1536,512]
__device__ float gWoutT[262144];   // [512,512]
__device__ float gPart[4194304];   // [8][BH][M][64] split-flash partials
__device__ float gMS[131072];      // [8][BH][M][2] split (m, s)
__device__ int   gMaxBits;

// ================= helpers =================
__device__ __forceinline__ uint32_t smem_u32(const void* p) {
    uint32_t a;
    asm("{ .reg .u64 t; cvta.to.shared.u64 t, %1; cvt.u32.u64 %0, t; }" : "=r"(a) : "l"(p));
    return a;
}
__device__ __forceinline__ float tf32r(float v) {
    uint32_t u;
    asm("cvt.rna.tf32.f32 %0, %1;" : "=r"(u) : "f"(v));
    return __uint_as_float(u);
}
__device__ __forceinline__ void mma_16x8x8(float* c, const uint32_t* a, const uint32_t* b) {
    asm volatile("mma.sync.aligned.m16n8k8.row.col.f32.tf32.tf32.f32 "
                 "{%0,%1,%2,%3}, {%4,%5,%6,%7}, {%8,%9}, {%0,%1,%2,%3};"
                 : "+f"(c[0]), "+f"(c[1]), "+f"(c[2]), "+f"(c[3])
                 : "r"(a[0]), "r"(a[1]), "r"(a[2]), "r"(a[3]), "r"(b[0]), "r"(b[1]));
}
__device__ __forceinline__ void cp16(uint32_t dst, const float* src) {
    asm volatile("cp.async.cg.shared.global [%0], [%1], 16;" :: "r"(dst), "l"(src) : "memory");
}
#define CP_COMMIT() asm volatile("cp.async.commit_group;" ::: "memory")
#define CP_WAIT2()  asm volatile("cp.async.wait_group 2;" ::: "memory")
#define CP_WAIT1()  asm volatile("cp.async.wait_group 1;" ::: "memory")
#define CP_WAIT0()  asm volatile("cp.async.wait_group 0;" ::: "memory")

// Stage layout for big GEMM: 3 stages; each stage = A(128x36) + B(128x36) floats
#define ROWS_ 36
#define STAGE_F (2 * 128 * ROWS_)
#define PS 132
#define DYN_SMEM (3 * STAGE_F * 4)      // 110592 B -> 2 blocks/SM

// Small-tile (64x64) GEMM: 3 stages; each stage = A(64x36) + B(64x36)
#define STAGE64_F (2 * 64 * ROWS_)
#define PSS 68
#define DYN_SMEM64 (3 * STAGE64_F * 4)  // 55296 B -> 4 blocks/SM

// ---- big GEMM mainloop: 128x128 tile, 4 warps (warp tile 64x64), 1 sync/chunk ----
// Per kf: 16 A-LDS + 16 B-LDS feed 32 mma (1.0 LDS/mma).
__device__ __forceinline__ void mma_mainloop(
    const float* __restrict__ Ab, const float* __restrict__ Bb, int Kd,
    int tid, int warp_m, int warp_n, int g, int t,
    float acc[4][8][4], float* smem)
{
    const int nCh = Kd >> 5;
    const int r_cp = tid >> 3;          // 0..15
    const int k4_cp = (tid & 7) * 4;

#pragma unroll
    for (int s = 0; s < 2; s++) {
        float* base = smem + s * STAGE_F;
        uint32_t aB = smem_u32(base), bB = smem_u32(base + 128 * ROWS_);
#pragma unroll
        for (int i = 0; i < 8; i++) {
            int r = r_cp + i * 16;
            cp16(aB + (r * ROWS_ + k4_cp) * 4, Ab + (long long)r * Kd + s * 32 + k4_cp);
            cp16(bB + (r * ROWS_ + k4_cp) * 4, Bb + (long long)r * Kd + s * 32 + k4_cp);
        }
        CP_COMMIT();
    }

    for (int c = 0; c < nCh; c++) {
        CP_WAIT1();
        __syncthreads();
        if (c + 2 < nCh) {
            float* base = smem + ((c + 2) % 3) * STAGE_F;
            uint32_t aB = smem_u32(base), bB = smem_u32(base + 128 * ROWS_);
#pragma unroll
            for (int i = 0; i < 8; i++) {
                int r = r_cp + i * 16;
                cp16(aB + (r * ROWS_ + k4_cp) * 4,
                     Ab + (long long)r * Kd + (c + 2) * 32 + k4_cp);
                cp16(bB + (r * ROWS_ + k4_cp) * 4,
                     Bb + (long long)r * Kd + (c + 2) * 32 + k4_cp);
            }
        }
        CP_COMMIT();

        const float* sA = smem + (c % 3) * STAGE_F;
        const float* sB = sA + 128 * ROWS_;
#pragma unroll
        for (int kf = 0; kf < 4; kf++) {
            uint32_t a[4][4], b[8][2];
            const int co = kf * 8 + t;
#pragma unroll
            for (int mi = 0; mi < 4; mi++) {
                int r = warp_m * 64 + mi * 16 + g;
                a[mi][0] = __float_as_uint(sA[r * ROWS_ + co]);
                a[mi][1] = __float_as_uint(sA[(r + 8) * ROWS_ + co]);
                a[mi][2] = __float_as_uint(sA[r * ROWS_ + co + 4]);
                a[mi][3] = __float_as_uint(sA[(r + 8) * ROWS_ + co + 4]);
            }
#pragma unroll
            for (int nf = 0; nf < 8; nf++) {
                int rb = warp_n * 64 + nf * 8 + g;
                b[nf][0] = __float_as_uint(sB[rb * ROWS_ + co]);
                b[nf][1] = __float_as_uint(sB[rb * ROWS_ + co + 4]);
            }
#pragma unroll
            for (int mi = 0; mi < 4; mi++)
#pragma unroll
                for (int nf = 0; nf < 8; nf++)
                    mma_16x8x8(acc[mi][nf], a[mi], b[nf]);
        }
    }
    CP_WAIT0();
    __syncthreads();
}

// stash accumulators to padded smem (warp tile 64x64)
__device__ __forceinline__ void stash_pad(float acc[4][8][4], float* pad,
                                          int warp_m, int warp_n, int g, int t)
{
#pragma unroll
    for (int mi = 0; mi < 4; mi++) {
        int r0 = warp_m * 64 + mi * 16 + g;
#pragma unroll
        for (int nf = 0; nf < 8; nf++) {
            int c0 = warp_n * 64 + nf * 8 + 2 * t;
            pad[r0 * PS + c0]           = acc[mi][nf][0];
            pad[r0 * PS + c0 + 1]       = acc[mi][nf][1];
            pad[(r0 + 8) * PS + c0]     = acc[mi][nf][2];
            pad[(r0 + 8) * PS + c0 + 1] = acc[mi][nf][3];
        }
    }
}

// ======== generic tf32 mma NT GEMM (m-tile = blockIdx.y, n-tile = blockIdx.x) ========
__global__ __launch_bounds__(128) void gemm_mma(
    const float* __restrict__ A, const float* __restrict__ Bop,
    float* C, float* CT, const float* __restrict__ bias,
    int Kd, int ldc, int ldct,
    long long sA, long long sB, long long sC, long long sCT,
    float s, float dI, float sT, float dT, int rc)
{
    extern __shared__ float dynf[];
    const int tid = threadIdx.x;
    const int wid = tid >> 5, lane = tid & 31;
    const int warp_m = wid >> 1, warp_n = wid & 1;
    const int g = lane >> 2, t = lane & 3;
    const int m0 = blockIdx.y * 128, n0 = blockIdx.x * 128;
    const float* Ab = A + blockIdx.z * sA + (long long)m0 * Kd;
    const float* Bb = Bop + blockIdx.z * sB + (long long)n0 * Kd;

    float acc[4][8][4];
#pragma unroll
    for (int mi = 0; mi < 4; mi++)
#pragma unroll
        for (int nf = 0; nf < 8; nf++)
#pragma unroll
            for (int rr = 0; rr < 4; rr++) acc[mi][nf][rr] = 0.f;

    mma_mainloop(Ab, Bb, Kd, tid, warp_m, warp_n, g, t, acc, dynf);

    float* pad = dynf;
    stash_pad(acc, pad, warp_m, warp_n, g, t);
    __syncthreads();

    if (C) {
        float* Cb = C + blockIdx.z * sC;
#pragma unroll
        for (int rr = 0; rr < 32; rr++) {
            int rl = rr * 4 + wid;
            int grow = m0 + rl;
            float4 v = *(float4*)(pad + rl * PS + lane * 4);
            int gc = n0 + lane * 4;
            float o[4] = {v.x, v.y, v.z, v.w};
#pragma unroll
            for (int u = 0; u < 4; u++) {
                o[u] *= s;
                if (dI != 0.f && grow == gc + u) o[u] += dI;
                if (bias) o[u] += __ldg(bias + gc + u);
                if (rc) o[u] = tf32r(o[u]);
            }
            *(float4*)(Cb + (long long)grow * ldc + gc) = make_float4(o[0], o[1], o[2], o[3]);
        }
    }
    if (CT) {
        float* CTb = CT + blockIdx.z * sCT;
#pragma unroll
        for (int rr = 0; rr < 32; rr++) {
            int cl = rr * 4 + wid;
            int gcol = n0 + cl;
            int rbase = lane * 4;
            float o[4];
#pragma unroll
            for (int u = 0; u < 4; u++) {
                float v = sT * pad[(rbase + u) * PS + cl];
                if (dT != 0.f && gcol == m0 + rbase + u) v += dT;
                if (rc) v = tf32r(v);
                o[u] = v;
            }
            *(float4*)(CTb + (long long)gcol * ldct + m0 + rbase) =
                make_float4(o[0], o[1], o[2], o[3]);
        }
    }
}

// ======== tf32 mma qkv GEMM: scatter epilogue, outputs tf32-rounded ========
__global__ __launch_bounds__(128) void gemm_mma_qkv(
    const float* __restrict__ A, const float* __restrict__ Bop,
    float* __restrict__ Q, float* __restrict__ Kp, float* __restrict__ V)
{
    extern __shared__ float dynf[];
    const int tid = threadIdx.x;
    const int wid = tid >> 5, lane = tid & 31;
    const int warp_m = wid >> 1, warp_n = wid & 1;
    const int g = lane >> 2, t = lane & 3;
    const int m0 = blockIdx.y * 128, n0 = blockIdx.x * 128;
    const float* Ab = A + (long long)m0 * 512;
    const float* Bb = Bop + (long long)n0 * 512;

    float acc[4][8][4];
#pragma unroll
    for (int mi = 0; mi < 4; mi++)
#pragma unroll
        for (int nf = 0; nf < 8; nf++)
#pragma unroll
            for (int rr = 0; rr < 4; rr++) acc[mi][nf][rr] = 0.f;

    mma_mainloop(Ab, Bb, 512, tid, warp_m, warp_n, g, t, acc, dynf);

    float* pad = dynf;
    stash_pad(acc, pad, warp_m, warp_n, g, t);
    __syncthreads();

    const int which = n0 >> 9;
    float* dst = (which == 0) ? Q : ((which == 1) ? Kp : V);
    const float sc = (which == 0) ? 0.125f : 1.f;
#pragma unroll
    for (int rr = 0; rr < 32; rr++) {
        int rl = rr * 4 + wid;
        int grow = m0 + rl;
        int bidx = grow >> 13, n = grow & (N_ - 1);
        int gc = n0 + lane * 4;
        int h = (gc >> 6) & 7, d = gc & 63;
        float4 v = *(float4*)(pad + rl * PS + lane * 4);
        v.x = tf32r(v.x * sc); v.y = tf32r(v.y * sc);
        v.z = tf32r(v.z * sc); v.w = tf32r(v.w * sc);
        long long addr = ((long long)(bidx * 8 + h) * N_ + n) * 64 + d;
        *(float4*)(dst + addr) = v;
    }
}

// ======== small 64x64-tile tf32 mma NT GEMM (1 sync/chunk) ========
__global__ __launch_bounds__(128, 4) void gemm_mma64(
    const float* __restrict__ A, const float* __restrict__ Bop,
    float* C, float* CT,
    int Kd, int ldc, int ldct,
    long long sA, long long sB, long long sC, long long sCT,
    float s, float dI, float sT, float dT, int rc)
{
    extern __shared__ float dynf[];
    const int tid = threadIdx.x;
    const int wid = tid >> 5, lane = tid & 31;
    const int warp_m = wid >> 1, warp_n = wid & 1;
    const int g = lane >> 2, t = lane & 3;
    const int m0 = blockIdx.y * 64, n0 = blockIdx.x * 64;
    const float* Ab = A + blockIdx.z * sA + (long long)m0 * Kd;
    const float* Bb = Bop + blockIdx.z * sB + (long long)n0 * Kd;

    float acc[2][4][4];
#pragma unroll
    for (int mi = 0; mi < 2; mi++)
#pragma unroll
        for (int nf = 0; nf < 4; nf++)
#pragma unroll
            for (int rr = 0; rr < 4; rr++) acc[mi][nf][rr] = 0.f;

    const int nCh = Kd >> 5;
    const int r_cp = tid >> 3;
    const int k4_cp = (tid & 7) * 4;

#pragma unroll
    for (int sgn = 0; sgn < 2; sgn++) {
        float* base = dynf + sgn * STAGE64_F;
        uint32_t aB = smem_u32(base), bB = smem_u32(base + 64 * ROWS_);
#pragma unroll
        for (int i = 0; i < 4; i++) {
            int r = r_cp + i * 16;
            cp16(aB + (r * ROWS_ + k4_cp) * 4, Ab + (long long)r * Kd + sgn * 32 + k4_cp);
            cp16(bB + (r * ROWS_ + k4_cp) * 4, Bb + (long long)r * Kd + sgn * 32 + k4_cp);
        }
        CP_COMMIT();
    }

    for (int c = 0; c < nCh; c++) {
        CP_WAIT1();
        __syncthreads();
        if (c + 2 < nCh) {
            float* base = dynf + ((c + 2) % 3) * STAGE64_F;
            uint32_t aB = smem_u32(base), bB = smem_u32(base + 64 * ROWS_);
#pragma unroll
            for (int i = 0; i < 4; i++) {
                int r = r_cp + i * 16;
                cp16(aB + (r * ROWS_ + k4_cp) * 4,
                     Ab + (long long)r * Kd + (c + 2) * 32 + k4_cp);
                cp16(bB + (r * ROWS_ + k4_cp) * 4,
                     Bb + (long long)r * Kd + (c + 2) * 32 + k4_cp);
            }
        }
        CP_COMMIT();

        const float* sAm = dynf + (c % 3) * STAGE64_F;
        const float* sBm = sAm + 64 * ROWS_;
#pragma unroll
        for (int kf = 0; kf < 4; kf++) {
            uint32_t a[2][4], b[4][2];
            const int co = kf * 8 + t;
#pragma unroll
            for (int mi = 0; mi < 2; mi++) {
                int r = warp_m * 32 + mi * 16 + g;
                a[mi][0] = __float_as_uint(sAm[r * ROWS_ + co]);
                a[mi][1] = __float_as_uint(sAm[(r + 8) * ROWS_ + co]);
                a[mi][2] = __float_as_uint(sAm[r * ROWS_ + co + 4]);
                a[mi][3] = __float_as_uint(sAm[(r + 8) * ROWS_ + co + 4]);
            }
#pragma unroll
            for (int nf = 0; nf < 4; nf++) {
                int rb = warp_n * 32 + nf * 8 + g;
                b[nf][0] = __float_as_uint(sBm[rb * ROWS_ + co]);
                b[nf][1] = __float_as_uint(sBm[rb * ROWS_ + co + 4]);
            }
#pragma unroll
            for (int mi = 0; mi < 2; mi++)
#pragma unroll
                for (int nf = 0; nf < 4; nf++)
                    mma_16x8x8(acc[mi][nf], a[mi], b[nf]);
        }
    }
    CP_WAIT0();
    __syncthreads();

    float* pad = dynf;
#pragma unroll
    for (int mi = 0; mi < 2; mi++) {
        int r0 = warp_m * 32 + mi * 16 + g;
#pragma unroll
        for (int nf = 0; nf < 4; nf++) {
            int c0 = warp_n * 32 + nf * 8 + 2 * t;
            pad[r0 * PSS + c0]           = acc[mi][nf][0];
            pad[r0 * PSS + c0 + 1]       = acc[mi][nf][1];
            pad[(r0 + 8) * PSS + c0]     = acc[mi][nf][2];
            pad[(r0 + 8) * PSS + c0 + 1] = acc[mi][nf][3];
        }
    }
    __syncthreads();

    if (C) {
        float* Cb = C + blockIdx.z * sC;
#pragma unroll
        for (int i = 0; i < 8; i++) {
            int f = tid + i * 128;
            int r = f >> 4, c4 = (f & 15) * 4;
            int grow = m0 + r, gc = n0 + c4;
            float o[4];
#pragma unroll
            for (int u = 0; u < 4; u++) {
                float v = s * pad[r * PSS + c4 + u];
                if (dI != 0.f && grow == gc + u) v += dI;
                if (rc) v = tf32r(v);
                o[u] = v;
            }
            *(float4*)(Cb + (long long)grow * ldc + gc) = make_float4(o[0], o[1], o[2], o[3]);
        }
    }
    if (CT) {
        float* CTb = CT + blockIdx.z * sCT;
#pragma unroll
        for (int i = 0; i < 32; i++) {
            int f = tid + i * 128;
            int outr = f >> 6, outc = f & 63;
            float v = sT * pad[outc * PSS + outr];
            if (dT != 0.f && (n0 + outr) == (m0 + outc)) v += dT;
            if (rc) v = tf32r(v);
            CTb[(long long)(n0 + outr) * ldct + m0 + outc] = v;
        }
    }
}

// ======== fused flash attention on tensor cores, split-K capable ========
#define AST 68
#define DYN_ATTN ((6 * 64 * AST + 64) * 4)

__global__ __launch_bounds__(256, 2) void fused_attn_mma(
    const float* __restrict__ Arows, const float* __restrict__ Bmat,
    const float* __restrict__ Vmat, float* __restrict__ Out,
    int tilesPerSplit, int nChunks,
    long long sA, long long sB, long long sO, float* __restrict__ ms)
{
    extern __shared__ float dynf[];
    float* sAq = dynf;                 // [64][AST]
    float* sKb[2] = {sAq + 64 * AST, sAq + 2 * 64 * AST};
    float* sVb[2] = {sAq + 3 * 64 * AST, sAq + 4 * 64 * AST};
    float* sP  = sAq + 5 * 64 * AST;   // [64][AST]
    float* sCr = sP + 64 * AST;        // [64]

    const int tid = threadIdx.x;
    const int wid = tid >> 5, lane = tid & 31;
    const int warp_m = wid >> 2, warp_n = wid & 3;
    const int g = lane >> 2, t = lane & 3;
    const int bh = blockIdx.y;
    const int split = blockIdx.x / tilesPerSplit;
    const int tile = blockIdx.x - split * tilesPerSplit;
    const int row0 = tile * 64;
    const float* Ab = Arows + bh * sA + (long long)row0 * 64;
    const float* Bb = Bmat + bh * sB + (long long)split * nChunks * 64 * 64;
    const float* Vb = Vmat + bh * sB + (long long)split * nChunks * 64 * 64;
    float* Ob = Out + (long long)(split * gridDim.y + bh) * sO + (long long)row0 * 64;

#pragma unroll
    for (int i = 0; i < 4; i++) {
        int f = tid + i * 256;
        int r = f >> 4, c4 = (f & 15) * 4;
        *(float4*)&sAq[r * AST + c4] = *(const float4*)(Ab + (long long)r * 64 + c4);
    }

    {
        uint32_t dk = smem_u32(sKb[0]), dv = smem_u32(sVb[0]);
#pragma unroll
        for (int i = 0; i < 4; i++) {
            int gk = tid + i * 256;
            int r = gk >> 4, cc = (gk & 15) * 4;
            cp16(dk + (r * AST + cc) * 4, Bb + (long long)r * 64 + cc);
            cp16(dv + (r * AST + cc) * 4, Vb + (long long)r * 64 + cc);
        }
        CP_COMMIT();
    }

    float acc_o[2][2][4];
#pragma unroll
    for (int mi = 0; mi < 2; mi++)
#pragma unroll
        for (int nf = 0; nf < 2; nf++)
#pragma unroll
            for (int rr = 0; rr < 4; rr++) acc_o[mi][nf][rr] = 0.f;

    const int sr = tid >> 2;
    const int cg = tid & 3;
    float mrun = -3.0e38f, srun = 0.f;

    for (int c = 0; c < nChunks; c++) {
        if (c + 1 < nChunks) {
            uint32_t dk = smem_u32(sKb[(c + 1) & 1]);
            uint32_t dv = smem_u32(sVb[(c + 1) & 1]);
            const float* Kg = Bb + (long long)(c + 1) * 64 * 64;
            const float* Vg = Vb + (long long)(c + 1) * 64 * 64;
#pragma unroll
            for (int i = 0; i < 4; i++) {
                int gk = tid + i * 256;
                int r = gk >> 4, cc = (gk & 15) * 4;
                cp16(dk + (r * AST + cc) * 4, Kg + (long long)r * 64 + cc);
                cp16(dv + (r * AST + cc) * 4, Vg + (long long)r * 64 + cc);
            }
        }
        CP_COMMIT();
        CP_WAIT1();
        __syncthreads();

        const float* cK = sKb[c & 1];
        const float* cV = sVb[c & 1];

        float acc_s[2][2][4];
#pragma unroll
        for (int mi = 0; mi < 2; mi++)
#pragma unroll
            for (int nf = 0; nf < 2; nf++)
#pragma unroll
                for (int rr = 0; rr < 4; rr++) acc_s[mi][nf][rr] = 0.f;
#pragma unroll
        for (int kf = 0; kf < 8; kf++) {
            const int co = kf * 8 + t;
            uint32_t a[2][4], b[2][2];
#pragma unroll
            for (int mi = 0; mi < 2; mi++) {
                int r = warp_m * 32 + mi * 16 + g;
                a[mi][0] = __float_as_uint(sAq[r * AST + co]);
                a[mi][1] = __float_as_uint(sAq[(r + 8) * AST + co]);
                a[mi][2] = __float_as_uint(sAq[r * AST + co + 4]);
                a[mi][3] = __float_as_uint(sAq[(r + 8) * AST + co + 4]);
            }
#pragma unroll
            for (int nf = 0; nf < 2; nf++) {
                int rb = warp_n * 16 + nf * 8 + g;
                b[nf][0] = __float_as_uint(cK[rb * AST + co]);
                b[nf][1] = __float_as_uint(cK[rb * AST + co + 4]);
            }
#pragma unroll
            for (int mi = 0; mi < 2; mi++)
#pragma unroll
                for (int nf = 0; nf < 2; nf++)
                    mma_16x8x8(acc_s[mi][nf], a[mi], b[nf]);
        }
#pragma unroll
        for (int mi = 0; mi < 2; mi++) {
            int r0 = warp_m * 32 + mi * 16 + g;
#pragma unroll
            for (int nf = 0; nf < 2; nf++) {
                int c0 = warp_n * 16 + nf * 8 + 2 * t;
                sP[r0 * AST + c0]           = acc_s[mi][nf][0];
                sP[r0 * AST + c0 + 1]       = acc_s[mi][nf][1];
                sP[(r0 + 8) * AST + c0]     = acc_s[mi][nf][2];
                sP[(r0 + 8) * AST + c0 + 1] = acc_s[mi][nf][3];
            }
        }
        __syncthreads();

        float v[16];
#pragma unroll
        for (int q = 0; q < 4; q++)
            *(float4*)&v[q * 4] = *(float4*)&sP[sr * AST + cg * 16 + q * 4];
        float mloc = v[0];
#pragma unroll
        for (int j = 1; j < 16; j++) mloc = fmaxf(mloc, v[j]);
        mloc = fmaxf(mloc, __shfl_xor_sync(0xffffffffu, mloc, 1));
        mloc = fmaxf(mloc, __shfl_xor_sync(0xffffffffu, mloc, 2));
        float mnew = fmaxf(mrun, mloc);
        float corr = __expf(mrun - mnew);
        float sl = 0.f;
#pragma unroll
        for (int j = 0; j < 16; j++) {
            float p = __expf(v[j] - mnew);
            v[j] = tf32r(p);
            sl += p;
        }
        sl += __shfl_xor_sync(0xffffffffu, sl, 1);
        sl += __shfl_xor_sync(0xffffffffu, sl, 2);
        srun = srun * corr + sl;
        mrun = mnew;
#pragma unroll
        for (int q = 0; q < 4; q++)
            *(float4*)&sP[sr * AST + cg * 16 + q * 4] = *(float4*)&v[q * 4];
        if (cg == 0) sCr[sr] = corr;
        __syncthreads();

#pragma unroll
        for (int mi = 0; mi < 2; mi++) {
            int r0 = warp_m * 32 + mi * 16 + g;
            float c0f = sCr[r0], c8f = sCr[r0 + 8];
#pragma unroll
            for (int nf = 0; nf < 2; nf++) {
                acc_o[mi][nf][0] *= c0f; acc_o[mi][nf][1] *= c0f;
                acc_o[mi][nf][2] *= c8f; acc_o[mi][nf][3] *= c8f;
            }
        }

#pragma unroll
        for (int kf = 0; kf < 8; kf++) {
            const int co = kf * 8 + t;
            uint32_t a[2][4], b[2][2];
#pragma unroll
            for (int mi = 0; mi < 2; mi++) {
                int r = warp_m * 32 + mi * 16 + g;
                a[mi][0] = __float_as_uint(sP[r * AST + co]);
                a[mi][1] = __float_as_uint(sP[(r + 8) * AST + co]);
                a[mi][2] = __float_as_uint(sP[r * AST + co + 4]);
                a[mi][3] = __float_as_uint(sP[(r + 8) * AST + co + 4]);
            }
#pragma unroll
            for (int nf = 0; nf < 2; nf++) {
                int d0 = warp_n * 16 + nf * 8 + g;
                b[nf][0] = __float_as_uint(cV[(kf * 8 + t) * AST + d0]);
                b[nf][1] = __float_as_uint(cV[(kf * 8 + t + 4) * AST + d0]);
            }
#pragma unroll
            for (int mi = 0; mi < 2; mi++)
#pragma unroll
                for (int nf = 0; nf < 2; nf++)
                    mma_16x8x8(acc_o[mi][nf], a[mi], b[nf]);
        }
        __syncthreads();
    }
    CP_WAIT0();

    if (cg == 0) {
        if (ms) {
            long long base = ((long long)(split * gridDim.y + bh) * (sO >> 6) + row0 + sr) * 2;
            ms[base] = mrun;
            ms[base + 1] = srun;
            sCr[sr] = 1.f;
        } else {
            sCr[sr] = 1.f / srun;
        }
    }
    __syncthreads();
#pragma unroll
    for (int mi = 0; mi < 2; mi++) {
        int r0 = warp_m * 32 + mi * 16 + g;
        float i0 = sCr[r0], i8 = sCr[r0 + 8];
#pragma unroll
        for (int nf = 0; nf < 2; nf++) {
            int c0 = warp_n * 16 + nf * 8 + 2 * t;
            sP[r0 * AST + c0]           = acc_o[mi][nf][0] * i0;
            sP[r0 * AST + c0 + 1]       = acc_o[mi][nf][1] * i0;
            sP[(r0 + 8) * AST + c0]     = acc_o[mi][nf][2] * i8;
            sP[(r0 + 8) * AST + c0 + 1] = acc_o[mi][nf][3] * i8;
        }
    }
    __syncthreads();
#pragma unroll
    for (int i = 0; i < 4; i++) {
        int f = tid + i * 256;
        int r = f >> 4, c4 = (f & 15) * 4;
        *(float4*)(Ob + (long long)r * 64 + c4) = *(float4*)&sP[r * AST + c4];
    }
}

// ---------------- split-flash combine: merge 8 partials per row ----------------
__global__ __launch_bounds__(256) void combine_kernel(
    const float* __restrict__ Part, const float* __restrict__ MS,
    float* __restrict__ Out)
{
    int gw = blockIdx.x * 8 + (threadIdx.x >> 5);
    int lane = threadIdx.x & 31;
    int bh = gw >> 8, row = gw & 255;
    float mv[8], sv[8];
    float Mx = -3.0e38f;
#pragma unroll
    for (int s = 0; s < 8; s++) {
        long long base = ((long long)(s * 32 + bh) * 256 + row) * 2;
        mv[s] = MS[base];
        sv[s] = MS[base + 1];
        Mx = fmaxf(Mx, mv[s]);
    }
    float S = 0.f, w[8];
#pragma unroll
    for (int s = 0; s < 8; s++) {
        w[s] = __expf(mv[s] - Mx);
        S += sv[s] * w[s];
    }
    float inv = 1.f / S;
    float o0 = 0.f, o1 = 0.f;
#pragma unroll
    for (int s = 0; s < 8; s++) {
        const float* P = Part + ((long long)(s * 32 + bh) * 256 + row) * 64;
        o0 += P[lane] * w[s];
        o1 += P[lane + 32] * w[s];
    }
    float* po = Out + ((long long)bh * 256 + row) * 64;
    po[lane] = o0 * inv;
    po[lane + 32] = o1 * inv;
}

// ---------------- weight transpose (+tf32 round) ----------------
__global__ void transpose_kernel(const float* __restrict__ src, float* __restrict__ dst,
                                 int R, int C)
{
    __shared__ float tbuf[32][33];
    int c0 = blockIdx.x * 32, r0 = blockIdx.y * 32;
    int x = threadIdx.x, y = threadIdx.y;
#pragma unroll
    for (int i = 0; i < 32; i += 8) tbuf[y + i][x] = src[(long long)(r0 + y + i) * C + c0 + x];
    __syncthreads();
#pragma unroll
    for (int i = 0; i < 32; i += 8)
        dst[(long long)(c0 + y + i) * R + r0 + x] = tf32r(tbuf[x][y + i]);
}

// ---------------- FFMA NN GEMM (W = Z @ A3V; outputs tf32-rounded) ----------------
__global__ __launch_bounds__(256) void gemm_nn(
    const float* __restrict__ A, const float* __restrict__ B,
    float* __restrict__ C, int Md, int Nd, int Kd,
    long long sA, long long sB, long long sC)
{
    A += (long long)blockIdx.z * sA;
    B += (long long)blockIdx.z * sB;
    C += (long long)blockIdx.z * sC;
    const int m0 = blockIdx.x * 128;
    const int n0 = blockIdx.y * 128;
    const int tid = threadIdx.x;
    const int tx = tid & 15, ty = tid >> 4;
    __shared__ float As[8][132];
    __shared__ float Bs[8][128];
    float acc[8][8];
#pragma unroll
    for (int i = 0; i < 8; i++)
#pragma unroll
        for (int j = 0; j < 8; j++) acc[i][j] = 0.f;
    const int ar = tid >> 1, ac = (tid & 1) * 4;
    const int bk = tid >> 5, bn = (tid & 31) * 4;
    const bool bok = (n0 + bn < Nd);
    for (int kk = 0; kk < Kd; kk += 8) {
        float4 av = *(const float4*)(A + (long long)(m0 + ar) * Kd + kk + ac);
        float4 bv = make_float4(0.f, 0.f, 0.f, 0.f);
        if (bok) bv = *(const float4*)(B + (long long)(kk + bk) * Nd + n0 + bn);
        As[ac + 0][ar] = av.x; As[ac + 1][ar] = av.y;
        As[ac + 2][ar] = av.z; As[ac + 3][ar] = av.w;
        *(float4*)&Bs[bk][bn] = bv;
        __syncthreads();
#pragma unroll
        for (int k = 0; k < 8; k++) {
            float a[8], b[8];
            *(float4*)&a[0] = *(const float4*)&As[k][ty * 8];
            *(float4*)&a[4] = *(const float4*)&As[k][ty * 8 + 4];
            *(float4*)&b[0] = *(const float4*)&Bs[k][tx * 8];
            *(float4*)&b[4] = *(const float4*)&Bs[k][tx * 8 + 4];
#pragma unroll
            for (int i = 0; i < 8; i++)
#pragma unroll
                for (int j = 0; j < 8; j++)
                    acc[i][j] = fmaf(a[i], b[j], acc[i][j]);
        }
        __syncthreads();
    }
#pragma unroll
    for (int i = 0; i < 8; i++) {
        int row = m0 + ty * 8 + i;
        if (row >= Md) continue;
#pragma unroll
        for (int jg = 0; jg < 8; jg += 4) {
            int col = n0 + tx * 8 + jg;
            if (col >= Nd) continue;
            float4 o = make_float4(tf32r(acc[i][jg]), tf32r(acc[i][jg + 1]),
                                   tf32r(acc[i][jg + 2]), tf32r(acc[i][jg + 3]));
            *(float4*)(C + (long long)row * Nd + col) = o;
        }
    }
}

// ---------------- landmark means for Q and K in one launch (+tf32 round) --------
__global__ void landmark_kernel(const float* __restrict__ Q, const float* __restrict__ K,
                                float* __restrict__ QL, float* __restrict__ KL)
{
    int m = blockIdx.x, bh = blockIdx.y, d = threadIdx.x;
    const float* src = blockIdx.z ? K : Q;
    float* dst = blockIdx.z ? KL : QL;
    const float* p = src + ((long long)bh * N_ + (long long)m * L_) * DH_ + d;
    float s = 0.f;
#pragma unroll
    for (int i = 0; i < L_; i++) s += p[i * DH_];
    dst[((long long)bh * M_ + m) * DH_ + d] = tf32r(s * (1.f / (float)L_));
}

__device__ __forceinline__ float warpMaxRed(float v) {
#pragma unroll
    for (int o = 16; o; o >>= 1) v = fmaxf(v, __shfl_xor_sync(0xffffffffu, v, o));
    return v;
}
__device__ __forceinline__ float warpSumRed(float v) {
#pragma unroll
    for (int o = 16; o; o >>= 1) v += __shfl_xor_sync(0xffffffffu, v, o);
    return v;
}

__global__ __launch_bounds__(256) void softmax_rows256(float* __restrict__ A)
{
    int warp = threadIdx.x >> 5, lane = threadIdx.x & 31;
    long long row = (long long)blockIdx.x * 8 + warp;
    float* p = A + row * 256;
    float4 v0 = *(float4*)(p + lane * 8);
    float4 v1 = *(float4*)(p + lane * 8 + 4);
    float mx = fmaxf(fmaxf(fmaxf(v0.x, v0.y), fmaxf(v0.z, v0.w)),
                     fmaxf(fmaxf(v1.x, v1.y), fmaxf(v1.z, v1.w)));
    mx = warpMaxRed(mx);
    v0.x = __expf(v0.x - mx); v0.y = __expf(v0.y - mx);
    v0.z = __expf(v0.z - mx); v0.w = __expf(v0.w - mx);
    v1.x = __expf(v1.x - mx); v1.y = __expf(v1.y - mx);
    v1.z = __expf(v1.z - mx); v1.w = __expf(v1.w - mx);
    float sm = v0.x + v0.y + v0.z + v0.w + v1.x + v1.y + v1.z + v1.w;
    sm = warpSumRed(sm);
    float inv = 1.f / sm;
    v0.x = tf32r(v0.x * inv); v0.y = tf32r(v0.y * inv);
    v0.z = tf32r(v0.z * inv); v0.w = tf32r(v0.w * inv);
    v1.x = tf32r(v1.x * inv); v1.y = tf32r(v1.y * inv);
    v1.z = tf32r(v1.z * inv); v1.w = tf32r(v1.w * inv);
    *(float4*)(p + lane * 8) = v0;
    *(float4*)(p + lane * 8 + 4) = v1;
}

// ---------------- pinv support ----------------
__global__ void init_max_kernel() { gMaxBits = 0; }

__global__ __launch_bounds__(256) void colmax_kernel(const float* __restrict__ A2)
{
    int bh = blockIdx.x, j = threadIdx.x;
    const float* p = A2 + ((long long)bh << 16) + j;
    float s = 0.f;
#pragma unroll 8
    for (int i = 0; i < 256; i++) s += p[i << 8];
    atomicMax(&gMaxBits, __float_as_int(s));
}

__global__ __launch_bounds__(256) void zinit_kernel(const float* __restrict__ A2,
                                                    float* __restrict__ Z,
                                                    float* __restrict__ ZT)
{
    int idx = blockIdx.x * 256 + threadIdx.x;
    float inv = 1.f / __int_as_float(gMaxBits);
    int bh = idx >> 16, r = idx & 65535, i = r >> 8, j = r & 255;
    Z[idx]  = tf32r(A2[(bh << 16) + (j << 8) + i] * inv);
    ZT[idx] = tf32r(A2[idx] * inv);
}

// ---------------- depthwise conv(k=33) + add + concat heads (+tf32 round) ----------
__global__ __launch_bounds__(256) void convcat_kernel(
    const float* __restrict__ V, const float* __restrict__ OH,
    const float* __restrict__ ker, float* __restrict__ CAT)
{
    int b = blockIdx.z, h = blockIdx.y, n0 = blockIdx.x * 64;
    int bh = b * H_ + h;
    __shared__ float sV[96][64];
    __shared__ float kw[33];
    int t = threadIdx.x;
    if (t < 33) kw[t] = ker[h * 33 + t];
    const float* Vb = V + (long long)bh * N_ * DH_;
    for (int idx = t; idx < 96 * 16; idx += 256) {
        int r = idx >> 4;
        int c4 = (idx & 15) * 4;
        int n = n0 - 16 + r;
        float4 val = make_float4(0.f, 0.f, 0.f, 0.f);
        if (n >= 0 && n < N_) val = *(const float4*)(Vb + (long long)n * DH_ + c4);
        *(float4*)&sV[r][c4] = val;
    }
    __syncthreads();
    int d = t & 63, nl0 = t >> 6;
#pragma unroll
    for (int ii = 0; ii < 16; ii++) {
        int nl = nl0 + ii * 4;
        float acc = 0.f;
#pragma unroll
        for (int tt = 0; tt < 33; tt++) acc = fmaf(sV[nl + tt][d], kw[tt], acc);
        int n = n0 + nl;
        float o = OH[((long long)bh * N_ + n) * DH_ + d] + acc;
        CAT[((long long)(b * N_ + n)) * 512 + h * 64 + d] = tf32r(o);
    }
}

// ---------------- host ----------------
extern "C" void kernel_launch(void* const* d_in, const int* in_sizes, int n_in,
                              void* d_out, int out_size)
{
    const float* x     = (const float*)d_in[0];
    const float* wqkv  = (const float*)d_in[1];
    const float* wout  = (const float*)d_in[2];
    const float* bout  = (const float*)d_in[3];
    const float* rker  = (const float*)d_in[4];
    float* out = (float*)d_out;

    cudaFuncSetAttribute(gemm_mma, cudaFuncAttributeMaxDynamicSharedMemorySize, DYN_SMEM);
    cudaFuncSetAttribute(gemm_mma_qkv, cudaFuncAttributeMaxDynamicSharedMemorySize, DYN_SMEM);
    cudaFuncSetAttribute(gemm_mma64, cudaFuncAttributeMaxDynamicSharedMemorySize, DYN_SMEM64);
    cudaFuncSetAttribute(fused_attn_mma, cudaFuncAttributeMaxDynamicSharedMemorySize, DYN_ATTN);

    float *pQ, *pK, *pV, *pQL, *pKL, *pA2, *pZ, *pZT, *pZ2, *pZ2T, *pX;
    float *pT1, *pT2, *pA3V, *pW, *pOH, *pCAT, *pWqkvT, *pWoutT, *pPart, *pMS;
    cudaGetSymbolAddress((void**)&pQ,  gQ);
    cudaGetSymbolAddress((void**)&pK,  gK);
    cudaGetSymbolAddress((void**)&pV,  gV);
    cudaGetSymbolAddress((void**)&pQL, gQL);
    cudaGetSymbolAddress((void**)&pKL, gKL);
    cudaGetSymbolAddress((void**)&pA2, gA2);
    cudaGetSymbolAddress((void**)&pZ,  gZ);
    cudaGetSymbolAddress((void**)&pZT, gZT);
    cudaGetSymbolAddress((void**)&pZ2, gZ2);
    cudaGetSymbolAddress((void**)&pZ2T, gZ2T);
    cudaGetSymbolAddress((void**)&pX,  gX);
    cudaGetSymbolAddress((void**)&pT1, gT1);
    cudaGetSymbolAddress((void**)&pT2, gT2);
    cudaGetSymbolAddress((void**)&pA3V, gA3V);
    cudaGetSymbolAddress((void**)&pW,  gW);
    cudaGetSymbolAddress((void**)&pOH, gOH);
    cudaGetSymbolAddress((void**)&pCAT, gCAT);
    cudaGetSymbolAddress((void**)&pWqkvT, gWqkvT);
    cudaGetSymbolAddress((void**)&pWoutT, gWoutT);
    cudaGetSymbolAddress((void**)&pPart, gPart);
    cudaGetSymbolAddress((void**)&pMS, gMS);

    const long long MM = (long long)M_ * M_;
    const long long MD = (long long)M_ * DH_;
    const long long ND = (long long)N_ * DH_;

    // 0) transpose+round weights (x fed raw: mma truncation ~= rounding)
    transpose_kernel<<<dim3(48, 16), dim3(32, 8)>>>(wqkv, pWqkvT, 512, 1536);
    transpose_kernel<<<dim3(16, 16), dim3(32, 8)>>>(wout, pWoutT, 512, 512);
    // 1) qkv GEMM with scatter epilogue (4-warp 64x64 warp tiles)
    gemm_mma_qkv<<<dim3(12, 256), 128, DYN_SMEM>>>(x, pWqkvT, pQ, pK, pV);
    // 2) landmarks (Q and K in one launch)
    landmark_kernel<<<dim3(M_, BH_, 2), DH_>>>(pQ, pK, pQL, pKL);
    // 3) attn2 = softmax(QL @ KL^T)
    gemm_mma64<<<dim3(4, 4, BH_), 128, DYN_SMEM64>>>(pQL, pKL, pA2, nullptr,
                                                     64, 256, 0, MD, MD, MM, 0,
                                                     1.f, 0.f, 0.f, 0.f, 0);
    softmax_rows256<<<1024, 256>>>(pA2);
    // 4) pinv init
    init_max_kernel<<<1, 1>>>();
    colmax_kernel<<<BH_, 256>>>(pA2);
    zinit_kernel<<<8192, 256>>>(pA2, pZ, pZT);
    // 5) Newton-Schulz iterations
    float *zin = pZ, *zinT = pZT, *zout = pZ2, *zoutT = pZ2T;
    for (int it = 0; it < 6; it++) {
        gemm_mma64<<<dim3(4, 4, BH_), 128, DYN_SMEM64>>>(pA2, zinT, pX, pT1,
                                                         256, 256, 256, MM, MM, MM, MM,
                                                         1.f, 0.f, -1.f, 7.f, 1);
        gemm_mma64<<<dim3(4, 4, BH_), 128, DYN_SMEM64>>>(pX, pT1, nullptr, pT2,
                                                         256, 256, 256, MM, MM, MM, MM,
                                                         0.f, 0.f, -1.f, 15.f, 1);
        gemm_mma64<<<dim3(4, 4, BH_), 128, DYN_SMEM64>>>(pX, pT2, nullptr, pT1,
                                                         256, 256, 256, MM, MM, MM, MM,
                                                         0.f, 0.f, -1.f, 13.f, 1);
        gemm_mma64<<<dim3(4, 4, BH_), 128, DYN_SMEM64>>>(zin, pT1, zout, zoutT,
                                                         256, 256, 256, MM, MM, MM, MM,
                                                         0.25f, 0.f, 0.25f, 0.f, 1);
        float* t;
        t = zin; zin = zout; zout = t;
        t = zinT; zinT = zoutT; zoutT = t;
    }
    // 6) A3V = softmax(QL @ K^T) @ V: split flash + combine
    fused_attn_mma<<<dim3(32, BH_), 256, DYN_ATTN>>>(pQL, pK, pV, pPart,
                                                     4, 16, MD, ND, MD, pMS);
    combine_kernel<<<1024, 256>>>(pPart, pMS, pA3V);
    // 7) W = Zfinal @ A3V (FFMA NN, outputs rounded)
    gemm_nn<<<dim3(2, 1, BH_), 256>>>(zin, pA3V, pW, 256, 64, 256, MM, MD, MD);
    // 8) OH = softmax(Q @ KL^T) @ W (non-split flash)
    fused_attn_mma<<<dim3(128, BH_), 256, DYN_ATTN>>>(pQ, pKL, pW, pOH,
                                                      128, 4, ND, MD, ND, nullptr);
    // 9) conv + concat
    convcat_kernel<<<dim3(128, H_, B_), 256>>>(pV, pOH, rker, pCAT);
    // 10) out = CAT @ wout + bout
    gemm_mma<<<dim3(4, 256), 128, DYN_SMEM>>>(pCAT, pWoutT, out, nullptr, bout,
                                              512, 512, 0, 0, 0, 0, 0,
                                              1.f, 0.f, 0.f, 0.f, 0);
}

// round 15
// speedup vs baseline: 1.0083x; 1.0083x over previous
#include <cuda_runtime.h>
#include <cstdint>
#include <math.h>

// Problem constants
#define B_   4
#define H_   8
#define N_   8192
#define DH_  64
#define M_   256
#define L_   32
#define BH_  32

// ---------------- scratch (device globals; no allocation anywhere) ----------------
__device__ float gQ[16777216];     // [BH,N,DH] (pre-scaled, tf32-rounded)
__device__ float gK[16777216];
__device__ float gV[16777216];
__device__ float gQL[524288];      // [BH,M,DH]
__device__ float gKL[524288];
__device__ float gA2[2097152];     // [BH,M,M] softmaxed (tf32-rounded)
__device__ float gZ [2097152];
__device__ float gZT[2097152];
__device__ float gZ2[2097152];
__device__ float gZ2T[2097152];
__device__ float gX [2097152];
__device__ float gT1[2097152];     // U1T / U3T
__device__ float gT2[2097152];     // U2T
__device__ float gA3V[524288];
__device__ float gW [524288];
__device__ float gOH[16777216];
__device__ float gCAT[16777216];   // conv output
__device__ float gWqkvT[786432];   // [1536,512]
__device__ float gWoutT[262144];   // [512,512]
__device__ float gPart[4194304];   // [8][BH][M][64] split-flash partials
__device__ float gMS[131072];      // [8][BH][M][2] split (m, s)
__device__ float gColMax[32];      // per-bh max col-sum

// ================= helpers =================
__device__ __forceinline__ uint32_t smem_u32(const void* p) {
    uint32_t a;
    asm("{ .reg .u64 t; cvta.to.shared.u64 t, %1; cvt.u32.u64 %0, t; }" : "=r"(a) : "l"(p));
    return a;
}
__device__ __forceinline__ float tf32r(float v) {
    uint32_t u;
    asm("cvt.rna.tf32.f32 %0, %1;" : "=r"(u) : "f"(v));
    return __uint_as_float(u);
}
__device__ __forceinline__ void mma_16x8x8(float* c, const uint32_t* a, const uint32_t* b) {
    asm volatile("mma.sync.aligned.m16n8k8.row.col.f32.tf32.tf32.f32 "
                 "{%0,%1,%2,%3}, {%4,%5,%6,%7}, {%8,%9}, {%0,%1,%2,%3};"
                 : "+f"(c[0]), "+f"(c[1]), "+f"(c[2]), "+f"(c[3])
                 : "r"(a[0]), "r"(a[1]), "r"(a[2]), "r"(a[3]), "r"(b[0]), "r"(b[1]));
}
__device__ __forceinline__ void cp16(uint32_t dst, const float* src) {
    asm volatile("cp.async.cg.shared.global [%0], [%1], 16;" :: "r"(dst), "l"(src) : "memory");
}
#define CP_COMMIT() asm volatile("cp.async.commit_group;" ::: "memory")
#define CP_WAIT1()  asm volatile("cp.async.wait_group 1;" ::: "memory")
#define CP_WAIT0()  asm volatile("cp.async.wait_group 0;" ::: "memory")

// Stage layout for big GEMM: 3 stages; each stage = A(128x36) + B(128x36) floats
#define ROWS_ 36
#define STAGE_F (2 * 128 * ROWS_)
#define PS 132
#define DYN_SMEM (3 * STAGE_F * 4)      // 110592 B -> 2 blocks/SM

// Small-tile (64x64) GEMM: 3 stages; each stage = A(64x36) + B(64x36)
#define STAGE64_F (2 * 64 * ROWS_)
#define PSS 68
#define DYN_SMEM64 (3 * STAGE64_F * 4)  // 55296 B -> 4 blocks/SM

// ---- big GEMM mainloop: 128x128 tile, 8 warps, K chunks of 32, 1 sync/chunk ----
__device__ __forceinline__ void mma_mainloop(
    const float* __restrict__ Ab, const float* __restrict__ Bb, int Kd,
    int tid, int warp_m, int warp_n, int g, int t,
    float acc[4][4][4], float* smem)
{
    const int nCh = Kd >> 5;
    const int r_cp = tid >> 3;
    const int k4_cp = (tid & 7) * 4;

#pragma unroll
    for (int s = 0; s < 2; s++) {
        float* base = smem + s * STAGE_F;
        uint32_t aB = smem_u32(base), bB = smem_u32(base + 128 * ROWS_);
#pragma unroll
        for (int i = 0; i < 4; i++) {
            int r = r_cp + i * 32;
            cp16(aB + (r * ROWS_ + k4_cp) * 4, Ab + (long long)r * Kd + s * 32 + k4_cp);
            cp16(bB + (r * ROWS_ + k4_cp) * 4, Bb + (long long)r * Kd + s * 32 + k4_cp);
        }
        CP_COMMIT();
    }

    for (int c = 0; c < nCh; c++) {
        CP_WAIT1();
        __syncthreads();
        if (c + 2 < nCh) {
            float* base = smem + ((c + 2) % 3) * STAGE_F;
            uint32_t aB = smem_u32(base), bB = smem_u32(base + 128 * ROWS_);
#pragma unroll
            for (int i = 0; i < 4; i++) {
                int r = r_cp + i * 32;
                cp16(aB + (r * ROWS_ + k4_cp) * 4,
                     Ab + (long long)r * Kd + (c + 2) * 32 + k4_cp);
                cp16(bB + (r * ROWS_ + k4_cp) * 4,
                     Bb + (long long)r * Kd + (c + 2) * 32 + k4_cp);
            }
        }
        CP_COMMIT();

        const float* sA = smem + (c % 3) * STAGE_F;
        const float* sB = sA + 128 * ROWS_;
#pragma unroll
        for (int kf = 0; kf < 4; kf++) {
            uint32_t a[4][4], b[4][2];
            const int co = kf * 8 + t;
#pragma unroll
            for (int mi = 0; mi < 4; mi++) {
                int r = warp_m * 64 + mi * 16 + g;
                a[mi][0] = __float_as_uint(sA[r * ROWS_ + co]);
                a[mi][1] = __float_as_uint(sA[(r + 8) * ROWS_ + co]);
                a[mi][2] = __float_as_uint(sA[r * ROWS_ + co + 4]);
                a[mi][3] = __float_as_uint(sA[(r + 8) * ROWS_ + co + 4]);
            }
#pragma unroll
            for (int nf = 0; nf < 4; nf++) {
                int rb = warp_n * 32 + nf * 8 + g;
                b[nf][0] = __float_as_uint(sB[rb * ROWS_ + co]);
                b[nf][1] = __float_as_uint(sB[rb * ROWS_ + co + 4]);
            }
#pragma unroll
            for (int mi = 0; mi < 4; mi++)
#pragma unroll
                for (int nf = 0; nf < 4; nf++)
                    mma_16x8x8(acc[mi][nf], a[mi], b[nf]);
        }
    }
    CP_WAIT0();
    __syncthreads();
}

// ======== generic tf32 mma NT GEMM (m-tile = blockIdx.y, n-tile = blockIdx.x) ========
__global__ __launch_bounds__(256) void gemm_mma(
    const float* __restrict__ A, const float* __restrict__ Bop,
    float* C, float* CT, const float* __restrict__ bias,
    int Kd, int ldc, int ldct,
    long long sA, long long sB, long long sC, long long sCT,
    float s, float dI, float sT, float dT, int rc)
{
    extern __shared__ float dynf[];
    const int tid = threadIdx.x;
    const int wid = tid >> 5, lane = tid & 31;
    const int warp_m = wid >> 2, warp_n = wid & 3;
    const int g = lane >> 2, t = lane & 3;
    const int m0 = blockIdx.y * 128, n0 = blockIdx.x * 128;
    const float* Ab = A + blockIdx.z * sA + (long long)m0 * Kd;
    const float* Bb = Bop + blockIdx.z * sB + (long long)n0 * Kd;

    float acc[4][4][4];
#pragma unroll
    for (int mi = 0; mi < 4; mi++)
#pragma unroll
        for (int nf = 0; nf < 4; nf++)
#pragma unroll
            for (int rr = 0; rr < 4; rr++) acc[mi][nf][rr] = 0.f;

    mma_mainloop(Ab, Bb, Kd, tid, warp_m, warp_n, g, t, acc, dynf);

    float* pad = dynf;
#pragma unroll
    for (int mi = 0; mi < 4; mi++) {
        int r0 = warp_m * 64 + mi * 16 + g;
#pragma unroll
        for (int nf = 0; nf < 4; nf++) {
            int c0 = warp_n * 32 + nf * 8 + 2 * t;
            pad[r0 * PS + c0]           = acc[mi][nf][0];
            pad[r0 * PS + c0 + 1]       = acc[mi][nf][1];
            pad[(r0 + 8) * PS + c0]     = acc[mi][nf][2];
            pad[(r0 + 8) * PS + c0 + 1] = acc[mi][nf][3];
        }
    }
    __syncthreads();

    if (C) {
        float* Cb = C + blockIdx.z * sC;
#pragma unroll
        for (int rr = 0; rr < 16; rr++) {
            int rl = rr * 8 + wid;
            int grow = m0 + rl;
            float4 v = *(float4*)(pad + rl * PS + lane * 4);
            int gc = n0 + lane * 4;
            float o[4] = {v.x, v.y, v.z, v.w};
#pragma unroll
            for (int u = 0; u < 4; u++) {
                o[u] *= s;
                if (dI != 0.f && grow == gc + u) o[u] += dI;
                if (bias) o[u] += __ldg(bias + gc + u);
                if (rc) o[u] = tf32r(o[u]);
            }
            *(float4*)(Cb + (long long)grow * ldc + gc) = make_float4(o[0], o[1], o[2], o[3]);
        }
    }
    if (CT) {
        float* CTb = CT + blockIdx.z * sCT;
#pragma unroll
        for (int rr = 0; rr < 16; rr++) {
            int cl = rr * 8 + wid;
            int gcol = n0 + cl;
            int rbase = lane * 4;
            float o[4];
#pragma unroll
            for (int u = 0; u < 4; u++) {
                float v = sT * pad[(rbase + u) * PS + cl];
                if (dT != 0.f && gcol == m0 + rbase + u) v += dT;
                if (rc) v = tf32r(v);
                o[u] = v;
            }
            *(float4*)(CTb + (long long)gcol * ldct + m0 + rbase) =
                make_float4(o[0], o[1], o[2], o[3]);
        }
    }
}

// ======== small 64x64-tile tf32 mma NT GEMM (1 sync/chunk) ========
__global__ __launch_bounds__(128, 4) void gemm_mma64(
    const float* __restrict__ A, const float* __restrict__ Bop,
    float* C, float* CT,
    int Kd, int ldc, int ldct,
    long long sA, long long sB, long long sC, long long sCT,
    float s, float dI, float sT, float dT, int rc)
{
    extern __shared__ float dynf[];
    const int tid = threadIdx.x;
    const int wid = tid >> 5, lane = tid & 31;
    const int warp_m = wid >> 1, warp_n = wid & 1;
    const int g = lane >> 2, t = lane & 3;
    const int m0 = blockIdx.y * 64, n0 = blockIdx.x * 64;
    const float* Ab = A + blockIdx.z * sA + (long long)m0 * Kd;
    const float* Bb = Bop + blockIdx.z * sB + (long long)n0 * Kd;

    float acc[2][4][4];
#pragma unroll
    for (int mi = 0; mi < 2; mi++)
#pragma unroll
        for (int nf = 0; nf < 4; nf++)
#pragma unroll
            for (int rr = 0; rr < 4; rr++) acc[mi][nf][rr] = 0.f;

    const int nCh = Kd >> 5;
    const int r_cp = tid >> 3;
    const int k4_cp = (tid & 7) * 4;

#pragma unroll
    for (int sgn = 0; sgn < 2; sgn++) {
        float* base = dynf + sgn * STAGE64_F;
        uint32_t aB = smem_u32(base), bB = smem_u32(base + 64 * ROWS_);
#pragma unroll
        for (int i = 0; i < 4; i++) {
            int r = r_cp + i * 16;
            cp16(aB + (r * ROWS_ + k4_cp) * 4, Ab + (long long)r * Kd + sgn * 32 + k4_cp);
            cp16(bB + (r * ROWS_ + k4_cp) * 4, Bb + (long long)r * Kd + sgn * 32 + k4_cp);
        }
        CP_COMMIT();
    }

    for (int c = 0; c < nCh; c++) {
        CP_WAIT1();
        __syncthreads();
        if (c + 2 < nCh) {
            float* base = dynf + ((c + 2) % 3) * STAGE64_F;
            uint32_t aB = smem_u32(base), bB = smem_u32(base + 64 * ROWS_);
#pragma unroll
            for (int i = 0; i < 4; i++) {
                int r = r_cp + i * 16;
                cp16(aB + (r * ROWS_ + k4_cp) * 4,
                     Ab + (long long)r * Kd + (c + 2) * 32 + k4_cp);
                cp16(bB + (r * ROWS_ + k4_cp) * 4,
                     Bb + (long long)r * Kd + (c + 2) * 32 + k4_cp);
            }
        }
        CP_COMMIT();

        const float* sAm = dynf + (c % 3) * STAGE64_F;
        const float* sBm = sAm + 64 * ROWS_;
#pragma unroll
        for (int kf = 0; kf < 4; kf++) {
            uint32_t a[2][4], b[4][2];
            const int co = kf * 8 + t;
#pragma unroll
            for (int mi = 0; mi < 2; mi++) {
                int r = warp_m * 32 + mi * 16 + g;
                a[mi][0] = __float_as_uint(sAm[r * ROWS_ + co]);
                a[mi][1] = __float_as_uint(sAm[(r + 8) * ROWS_ + co]);
                a[mi][2] = __float_as_uint(sAm[r * ROWS_ + co + 4]);
                a[mi][3] = __float_as_uint(sAm[(r + 8) * ROWS_ + co + 4]);
            }
#pragma unroll
            for (int nf = 0; nf < 4; nf++) {
                int rb = warp_n * 32 + nf * 8 + g;
                b[nf][0] = __float_as_uint(sBm[rb * ROWS_ + co]);
                b[nf][1] = __float_as_uint(sBm[rb * ROWS_ + co + 4]);
            }
#pragma unroll
            for (int mi = 0; mi < 2; mi++)
#pragma unroll
                for (int nf = 0; nf < 4; nf++)
                    mma_16x8x8(acc[mi][nf], a[mi], b[nf]);
        }
    }
    CP_WAIT0();
    __syncthreads();

    float* pad = dynf;
#pragma unroll
    for (int mi = 0; mi < 2; mi++) {
        int r0 = warp_m * 32 + mi * 16 + g;
#pragma unroll
        for (int nf = 0; nf < 4; nf++) {
            int c0 = warp_n * 32 + nf * 8 + 2 * t;
            pad[r0 * PSS + c0]           = acc[mi][nf][0];
            pad[r0 * PSS + c0 + 1]       = acc[mi][nf][1];
            pad[(r0 + 8) * PSS + c0]     = acc[mi][nf][2];
            pad[(r0 + 8) * PSS + c0 + 1] = acc[mi][nf][3];
        }
    }
    __syncthreads();

    if (C) {
        float* Cb = C + blockIdx.z * sC;
#pragma unroll
        for (int i = 0; i < 8; i++) {
            int f = tid + i * 128;
            int r = f >> 4, c4 = (f & 15) * 4;
            int grow = m0 + r, gc = n0 + c4;
            float o[4];
#pragma unroll
            for (int u = 0; u < 4; u++) {
                float v = s * pad[r * PSS + c4 + u];
                if (dI != 0.f && grow == gc + u) v += dI;
                if (rc) v = tf32r(v);
                o[u] = v;
            }
            *(float4*)(Cb + (long long)grow * ldc + gc) = make_float4(o[0], o[1], o[2], o[3]);
        }
    }
    if (CT) {
        float* CTb = CT + blockIdx.z * sCT;
#pragma unroll
        for (int i = 0; i < 32; i++) {
            int f = tid + i * 128;
            int outr = f >> 6, outc = f & 63;
            float v = sT * pad[outc * PSS + outr];
            if (dT != 0.f && (n0 + outr) == (m0 + outc)) v += dT;
            if (rc) v = tf32r(v);
            CTb[(long long)(n0 + outr) * ldct + m0 + outc] = v;
        }
    }
}

// ======== tf32 mma qkv GEMM: scatter epilogue, outputs tf32-rounded ========
__global__ __launch_bounds__(256) void gemm_mma_qkv(
    const float* __restrict__ A, const float* __restrict__ Bop,
    float* __restrict__ Q, float* __restrict__ Kp, float* __restrict__ V)
{
    extern __shared__ float dynf[];
    const int tid = threadIdx.x;
    const int wid = tid >> 5, lane = tid & 31;
    const int warp_m = wid >> 2, warp_n = wid & 3;
    const int g = lane >> 2, t = lane & 3;
    const int m0 = blockIdx.y * 128, n0 = blockIdx.x * 128;
    const float* Ab = A + (long long)m0 * 512;
    const float* Bb = Bop + (long long)n0 * 512;

    float acc[4][4][4];
#pragma unroll
    for (int mi = 0; mi < 4; mi++)
#pragma unroll
        for (int nf = 0; nf < 4; nf++)
#pragma unroll
            for (int rr = 0; rr < 4; rr++) acc[mi][nf][rr] = 0.f;

    mma_mainloop(Ab, Bb, 512, tid, warp_m, warp_n, g, t, acc, dynf);

    float* pad = dynf;
#pragma unroll
    for (int mi = 0; mi < 4; mi++) {
        int r0 = warp_m * 64 + mi * 16 + g;
#pragma unroll
        for (int nf = 0; nf < 4; nf++) {
            int c0 = warp_n * 32 + nf * 8 + 2 * t;
            pad[r0 * PS + c0]           = acc[mi][nf][0];
            pad[r0 * PS + c0 + 1]       = acc[mi][nf][1];
            pad[(r0 + 8) * PS + c0]     = acc[mi][nf][2];
            pad[(r0 + 8) * PS + c0 + 1] = acc[mi][nf][3];
        }
    }
    __syncthreads();

    const int which = n0 >> 9;
    float* dst = (which == 0) ? Q : ((which == 1) ? Kp : V);
    const float sc = (which == 0) ? 0.125f : 1.f;
#pragma unroll
    for (int rr = 0; rr < 16; rr++) {
        int rl = rr * 8 + wid;
        int grow = m0 + rl;
        int bidx = grow >> 13, n = grow & (N_ - 1);
        int gc = n0 + lane * 4;
        int h = (gc >> 6) & 7, d = gc & 63;
        float4 v = *(float4*)(pad + rl * PS + lane * 4);
        v.x = tf32r(v.x * sc); v.y = tf32r(v.y * sc);
        v.z = tf32r(v.z * sc); v.w = tf32r(v.w * sc);
        long long addr = ((long long)(bidx * 8 + h) * N_ + n) * 64 + d;
        *(float4*)(dst + addr) = v;
    }
}

// ======== fused flash attention on tensor cores, split-K capable ========
#define AST 68
#define DYN_ATTN ((6 * 64 * AST + 64) * 4)

__global__ __launch_bounds__(256, 2) void fused_attn_mma(
    const float* __restrict__ Arows, const float* __restrict__ Bmat,
    const float* __restrict__ Vmat, float* __restrict__ Out,
    int tilesPerSplit, int nChunks,
    long long sA, long long sB, long long sO, float* __restrict__ ms)
{
    extern __shared__ float dynf[];
    float* sAq = dynf;                 // [64][AST]
    float* sKb[2] = {sAq + 64 * AST, sAq + 2 * 64 * AST};
    float* sVb[2] = {sAq + 3 * 64 * AST, sAq + 4 * 64 * AST};
    float* sP  = sAq + 5 * 64 * AST;   // [64][AST]
    float* sCr = sP + 64 * AST;        // [64]

    const int tid = threadIdx.x;
    const int wid = tid >> 5, lane = tid & 31;
    const int warp_m = wid >> 2, warp_n = wid & 3;
    const int g = lane >> 2, t = lane & 3;
    const int bh = blockIdx.y;
    const int split = blockIdx.x / tilesPerSplit;
    const int tile = blockIdx.x - split * tilesPerSplit;
    const int row0 = tile * 64;
    const float* Ab = Arows + bh * sA + (long long)row0 * 64;
    const float* Bb = Bmat + bh * sB + (long long)split * nChunks * 64 * 64;
    const float* Vb = Vmat + bh * sB + (long long)split * nChunks * 64 * 64;
    float* Ob = Out + (long long)(split * gridDim.y + bh) * sO + (long long)row0 * 64;

#pragma unroll
    for (int i = 0; i < 4; i++) {
        int f = tid + i * 256;
        int r = f >> 4, c4 = (f & 15) * 4;
        *(float4*)&sAq[r * AST + c4] = *(const float4*)(Ab + (long long)r * 64 + c4);
    }

    {
        uint32_t dk = smem_u32(sKb[0]), dv = smem_u32(sVb[0]);
#pragma unroll
        for (int i = 0; i < 4; i++) {
            int gk = tid + i * 256;
            int r = gk >> 4, cc = (gk & 15) * 4;
            cp16(dk + (r * AST + cc) * 4, Bb + (long long)r * 64 + cc);
            cp16(dv + (r * AST + cc) * 4, Vb + (long long)r * 64 + cc);
        }
        CP_COMMIT();
    }

    float acc_o[2][2][4];
#pragma unroll
    for (int mi = 0; mi < 2; mi++)
#pragma unroll
        for (int nf = 0; nf < 2; nf++)
#pragma unroll
            for (int rr = 0; rr < 4; rr++) acc_o[mi][nf][rr] = 0.f;

    const int sr = tid >> 2;
    const int cg = tid & 3;
    float mrun = -3.0e38f, srun = 0.f;

    for (int c = 0; c < nChunks; c++) {
        if (c + 1 < nChunks) {
            uint32_t dk = smem_u32(sKb[(c + 1) & 1]);
            uint32_t dv = smem_u32(sVb[(c + 1) & 1]);
            const float* Kg = Bb + (long long)(c + 1) * 64 * 64;
            const float* Vg = Vb + (long long)(c + 1) * 64 * 64;
#pragma unroll
            for (int i = 0; i < 4; i++) {
                int gk = tid + i * 256;
                int r = gk >> 4, cc = (gk & 15) * 4;
                cp16(dk + (r * AST + cc) * 4, Kg + (long long)r * 64 + cc);
                cp16(dv + (r * AST + cc) * 4, Vg + (long long)r * 64 + cc);
            }
        }
        CP_COMMIT();
        CP_WAIT1();
        __syncthreads();

        const float* cK = sKb[c & 1];
        const float* cV = sVb[c & 1];

        float acc_s[2][2][4];
#pragma unroll
        for (int mi = 0; mi < 2; mi++)
#pragma unroll
            for (int nf = 0; nf < 2; nf++)
#pragma unroll
                for (int rr = 0; rr < 4; rr++) acc_s[mi][nf][rr] = 0.f;
#pragma unroll
        for (int kf = 0; kf < 8; kf++) {
            const int co = kf * 8 + t;
            uint32_t a[2][4], b[2][2];
#pragma unroll
            for (int mi = 0; mi < 2; mi++) {
                int r = warp_m * 32 + mi * 16 + g;
                a[mi][0] = __float_as_uint(sAq[r * AST + co]);
                a[mi][1] = __float_as_uint(sAq[(r + 8) * AST + co]);
                a[mi][2] = __float_as_uint(sAq[r * AST + co + 4]);
                a[mi][3] = __float_as_uint(sAq[(r + 8) * AST + co + 4]);
            }
#pragma unroll
            for (int nf = 0; nf < 2; nf++) {
                int rb = warp_n * 16 + nf * 8 + g;
                b[nf][0] = __float_as_uint(cK[rb * AST + co]);
                b[nf][1] = __float_as_uint(cK[rb * AST + co + 4]);
            }
#pragma unroll
            for (int mi = 0; mi < 2; mi++)
#pragma unroll
                for (int nf = 0; nf < 2; nf++)
                    mma_16x8x8(acc_s[mi][nf], a[mi], b[nf]);
        }
#pragma unroll
        for (int mi = 0; mi < 2; mi++) {
            int r0 = warp_m * 32 + mi * 16 + g;
#pragma unroll
            for (int nf = 0; nf < 2; nf++) {
                int c0 = warp_n * 16 + nf * 8 + 2 * t;
                sP[r0 * AST + c0]           = acc_s[mi][nf][0];
                sP[r0 * AST + c0 + 1]       = acc_s[mi][nf][1];
                sP[(r0 + 8) * AST + c0]     = acc_s[mi][nf][2];
                sP[(r0 + 8) * AST + c0 + 1] = acc_s[mi][nf][3];
            }
        }
        __syncthreads();

        float v[16];
#pragma unroll
        for (int q = 0; q < 4; q++)
            *(float4*)&v[q * 4] = *(float4*)&sP[sr * AST + cg * 16 + q * 4];
        float mloc = v[0];
#pragma unroll
        for (int j = 1; j < 16; j++) mloc = fmaxf(mloc, v[j]);
        mloc = fmaxf(mloc, __shfl_xor_sync(0xffffffffu, mloc, 1));
        mloc = fmaxf(mloc, __shfl_xor_sync(0xffffffffu, mloc, 2));
        float mnew = fmaxf(mrun, mloc);
        float corr = __expf(mrun - mnew);
        float sl = 0.f;
#pragma unroll
        for (int j = 0; j < 16; j++) {
            float p = __expf(v[j] - mnew);
            v[j] = p;                      // mma truncates to tf32 anyway
            sl += p;
        }
        sl += __shfl_xor_sync(0xffffffffu, sl, 1);
        sl += __shfl_xor_sync(0xffffffffu, sl, 2);
        srun = srun * corr + sl;
        mrun = mnew;
#pragma unroll
        for (int q = 0; q < 4; q++)
            *(float4*)&sP[sr * AST + cg * 16 + q * 4] = *(float4*)&v[q * 4];
        if (cg == 0) sCr[sr] = corr;
        __syncthreads();

#pragma unroll
        for (int mi = 0; mi < 2; mi++) {
            int r0 = warp_m * 32 + mi * 16 + g;
            float c0f = sCr[r0], c8f = sCr[r0 + 8];
#pragma unroll
            for (int nf = 0; nf < 2; nf++) {
                acc_o[mi][nf][0] *= c0f; acc_o[mi][nf][1] *= c0f;
                acc_o[mi][nf][2] *= c8f; acc_o[mi][nf][3] *= c8f;
            }
        }

#pragma unroll
        for (int kf = 0; kf < 8; kf++) {
            const int co = kf * 8 + t;
            uint32_t a[2][4], b[2][2];
#pragma unroll
            for (int mi = 0; mi < 2; mi++) {
                int r = warp_m * 32 + mi * 16 + g;
                a[mi][0] = __float_as_uint(sP[r * AST + co]);
                a[mi][1] = __float_as_uint(sP[(r + 8) * AST + co]);
                a[mi][2] = __float_as_uint(sP[r * AST + co + 4]);
                a[mi][3] = __float_as_uint(sP[(r + 8) * AST + co + 4]);
            }
#pragma unroll
            for (int nf = 0; nf < 2; nf++) {
                int d0 = warp_n * 16 + nf * 8 + g;
                b[nf][0] = __float_as_uint(cV[(kf * 8 + t) * AST + d0]);
                b[nf][1] = __float_as_uint(cV[(kf * 8 + t + 4) * AST + d0]);
            }
#pragma unroll
            for (int mi = 0; mi < 2; mi++)
#pragma unroll
                for (int nf = 0; nf < 2; nf++)
                    mma_16x8x8(acc_o[mi][nf], a[mi], b[nf]);
        }
        __syncthreads();
    }
    CP_WAIT0();

    if (cg == 0) {
        if (ms) {
            long long base = ((long long)(split * gridDim.y + bh) * (sO >> 6) + row0 + sr) * 2;
            ms[base] = mrun;
            ms[base + 1] = srun;
            sCr[sr] = 1.f;
        } else {
            sCr[sr] = 1.f / srun;
        }
    }
    __syncthreads();
#pragma unroll
    for (int mi = 0; mi < 2; mi++) {
        int r0 = warp_m * 32 + mi * 16 + g;
        float i0 = sCr[r0], i8 = sCr[r0 + 8];
#pragma unroll
        for (int nf = 0; nf < 2; nf++) {
            int c0 = warp_n * 16 + nf * 8 + 2 * t;
            sP[r0 * AST + c0]           = acc_o[mi][nf][0] * i0;
            sP[r0 * AST + c0 + 1]       = acc_o[mi][nf][1] * i0;
            sP[(r0 + 8) * AST + c0]     = acc_o[mi][nf][2] * i8;
            sP[(r0 + 8) * AST + c0 + 1] = acc_o[mi][nf][3] * i8;
        }
    }
    __syncthreads();
#pragma unroll
    for (int i = 0; i < 4; i++) {
        int f = tid + i * 256;
        int r = f >> 4, c4 = (f & 15) * 4;
        *(float4*)(Ob + (long long)r * 64 + c4) = *(float4*)&sP[r * AST + c4];
    }
}

// ---------------- split-flash combine: merge 8 partials per row ----------------
__global__ __launch_bounds__(256) void combine_kernel(
    const float* __restrict__ Part, const float* __restrict__ MS,
    float* __restrict__ Out)
{
    int gw = blockIdx.x * 8 + (threadIdx.x >> 5);
    int lane = threadIdx.x & 31;
    int bh = gw >> 8, row = gw & 255;
    float mv[8], sv[8];
    float Mx = -3.0e38f;
#pragma unroll
    for (int s = 0; s < 8; s++) {
        long long base = ((long long)(s * 32 + bh) * 256 + row) * 2;
        mv[s] = MS[base];
        sv[s] = MS[base + 1];
        Mx = fmaxf(Mx, mv[s]);
    }
    float S = 0.f, w[8];
#pragma unroll
    for (int s = 0; s < 8; s++) {
        w[s] = __expf(mv[s] - Mx);
        S += sv[s] * w[s];
    }
    float inv = 1.f / S;
    float o0 = 0.f, o1 = 0.f;
#pragma unroll
    for (int s = 0; s < 8; s++) {
        const float* P = Part + ((long long)(s * 32 + bh) * 256 + row) * 64;
        o0 += P[lane] * w[s];
        o1 += P[lane + 32] * w[s];
    }
    float* po = Out + ((long long)bh * 256 + row) * 64;
    po[lane] = o0 * inv;
    po[lane + 32] = o1 * inv;
}

// ---------------- weight transposes, both matrices in one launch (+tf32 round) ----
__global__ void transpose_kernel(const float* __restrict__ wqkv,
                                 const float* __restrict__ wout,
                                 float* __restrict__ wqkvT, float* __restrict__ woutT)
{
    __shared__ float tbuf[32][33];
    const float* src;
    float* dst;
    int R, C;
    int bx = blockIdx.x;
    if (bx < 48 * 16) { src = wqkv; dst = wqkvT; R = 512; C = 1536; }
    else { bx -= 48 * 16; src = wout; dst = woutT; R = 512; C = 512; }
    int nbx = C >> 5;
    int c0 = (bx % nbx) * 32, r0 = (bx / nbx) * 32;
    int x = threadIdx.x, y = threadIdx.y;
#pragma unroll
    for (int i = 0; i < 32; i += 8) tbuf[y + i][x] = src[(long long)(r0 + y + i) * C + c0 + x];
    __syncthreads();
#pragma unroll
    for (int i = 0; i < 32; i += 8)
        dst[(long long)(c0 + y + i) * R + r0 + x] = tf32r(tbuf[x][y + i]);
}

// ---------------- FFMA NN GEMM (W = Z @ A3V; outputs tf32-rounded) ----------------
__global__ __launch_bounds__(256) void gemm_nn(
    const float* __restrict__ A, const float* __restrict__ B,
    float* __restrict__ C, int Md, int Nd, int Kd,
    long long sA, long long sB, long long sC)
{
    A += (long long)blockIdx.z * sA;
    B += (long long)blockIdx.z * sB;
    C += (long long)blockIdx.z * sC;
    const int m0 = blockIdx.x * 128;
    const int n0 = blockIdx.y * 128;
    const int tid = threadIdx.x;
    const int tx = tid & 15, ty = tid >> 4;
    __shared__ float As[8][132];
    __shared__ float Bs[8][128];
    float acc[8][8];
#pragma unroll
    for (int i = 0; i < 8; i++)
#pragma unroll
        for (int j = 0; j < 8; j++) acc[i][j] = 0.f;
    const int ar = tid >> 1, ac = (tid & 1) * 4;
    const int bk = tid >> 5, bn = (tid & 31) * 4;
    const bool bok = (n0 + bn < Nd);
    for (int kk = 0; kk < Kd; kk += 8) {
        float4 av = *(const float4*)(A + (long long)(m0 + ar) * Kd + kk + ac);
        float4 bv = make_float4(0.f, 0.f, 0.f, 0.f);
        if (bok) bv = *(const float4*)(B + (long long)(kk + bk) * Nd + n0 + bn);
        As[ac + 0][ar] = av.x; As[ac + 1][ar] = av.y;
        As[ac + 2][ar] = av.z; As[ac + 3][ar] = av.w;
        *(float4*)&Bs[bk][bn] = bv;
        __syncthreads();
#pragma unroll
        for (int k = 0; k < 8; k++) {
            float a[8], b[8];
            *(float4*)&a[0] = *(const float4*)&As[k][ty * 8];
            *(float4*)&a[4] = *(const float4*)&As[k][ty * 8 + 4];
            *(float4*)&b[0] = *(const float4*)&Bs[k][tx * 8];
            *(float4*)&b[4] = *(const float4*)&Bs[k][tx * 8 + 4];
#pragma unroll
            for (int i = 0; i < 8; i++)
#pragma unroll
                for (int j = 0; j < 8; j++)
                    acc[i][j] = fmaf(a[i], b[j], acc[i][j]);
        }
        __syncthreads();
    }
#pragma unroll
    for (int i = 0; i < 8; i++) {
        int row = m0 + ty * 8 + i;
        if (row >= Md) continue;
#pragma unroll
        for (int jg = 0; jg < 8; jg += 4) {
            int col = n0 + tx * 8 + jg;
            if (col >= Nd) continue;
            float4 o = make_float4(tf32r(acc[i][jg]), tf32r(acc[i][jg + 1]),
                                   tf32r(acc[i][jg + 2]), tf32r(acc[i][jg + 3]));
            *(float4*)(C + (long long)row * Nd + col) = o;
        }
    }
}

// ---------------- landmark means for Q and K in one launch (+tf32 round) --------
__global__ void landmark_kernel(const float* __restrict__ Q, const float* __restrict__ K,
                                float* __restrict__ QL, float* __restrict__ KL)
{
    int m = blockIdx.x, bh = blockIdx.y, d = threadIdx.x;
    const float* src = blockIdx.z ? K : Q;
    float* dst = blockIdx.z ? KL : QL;
    const float* p = src + ((long long)bh * N_ + (long long)m * L_) * DH_ + d;
    float s = 0.f;
#pragma unroll
    for (int i = 0; i < L_; i++) s += p[i * DH_];
    dst[((long long)bh * M_ + m) * DH_ + d] = tf32r(s * (1.f / (float)L_));
}

__device__ __forceinline__ float warpMaxRed(float v) {
#pragma unroll
    for (int o = 16; o; o >>= 1) v = fmaxf(v, __shfl_xor_sync(0xffffffffu, v, o));
    return v;
}
__device__ __forceinline__ float warpSumRed(float v) {
#pragma unroll
    for (int o = 16; o; o >>= 1) v += __shfl_xor_sync(0xffffffffu, v, o);
    return v;
}

__global__ __launch_bounds__(256) void softmax_rows256(float* __restrict__ A)
{
    int warp = threadIdx.x >> 5, lane = threadIdx.x & 31;
    long long row = (long long)blockIdx.x * 8 + warp;
    float* p = A + row * 256;
    float4 v0 = *(float4*)(p + lane * 8);
    float4 v1 = *(float4*)(p + lane * 8 + 4);
    float mx = fmaxf(fmaxf(fmaxf(v0.x, v0.y), fmaxf(v0.z, v0.w)),
                     fmaxf(fmaxf(v1.x, v1.y), fmaxf(v1.z, v1.w)));
    mx = warpMaxRed(mx);
    v0.x = __expf(v0.x - mx); v0.y = __expf(v0.y - mx);
    v0.z = __expf(v0.z - mx); v0.w = __expf(v0.w - mx);
    v1.x = __expf(v1.x - mx); v1.y = __expf(v1.y - mx);
    v1.z = __expf(v1.z - mx); v1.w = __expf(v1.w - mx);
    float sm = v0.x + v0.y + v0.z + v0.w + v1.x + v1.y + v1.z + v1.w;
    sm = warpSumRed(sm);
    float inv = 1.f / sm;
    v0.x = tf32r(v0.x * inv); v0.y = tf32r(v0.y * inv);
    v0.z = tf32r(v0.z * inv); v0.w = tf32r(v0.w * inv);
    v1.x = tf32r(v1.x * inv); v1.y = tf32r(v1.y * inv);
    v1.z = tf32r(v1.z * inv); v1.w = tf32r(v1.w * inv);
    *(float4*)(p + lane * 8) = v0;
    *(float4*)(p + lane * 8 + 4) = v1;
}

// ---------------- pinv support: per-bh col-sum max (no global atomic) ----------
__global__ __launch_bounds__(256) void colmax_kernel(const float* __restrict__ A2,
                                                     float* __restrict__ ColMax)
{
    int bh = blockIdx.x, j = threadIdx.x;
    const float* p = A2 + ((long long)bh << 16) + j;
    float s = 0.f;
#pragma unroll 8
    for (int i = 0; i < 256; i++) s += p[i << 8];
    __shared__ float red[8];
    float wm = warpMaxRed(s);
    if ((j & 31) == 0) red[j >> 5] = wm;
    __syncthreads();
    if (j == 0) {
        float m = red[0];
#pragma unroll
        for (int w = 1; w < 8; w++) m = fmaxf(m, red[w]);
        ColMax[bh] = m;
    }
}

__global__ __launch_bounds__(256) void zinit_kernel(const float* __restrict__ A2,
                                                    const float* __restrict__ ColMax,
                                                    float* __restrict__ Z,
                                                    float* __restrict__ ZT)
{
    __shared__ float sInv;
    if (threadIdx.x == 0) {
        float m = ColMax[0];
#pragma unroll
        for (int w = 1; w < 32; w++) m = fmaxf(m, ColMax[w]);
        sInv = 1.f / m;
    }
    __syncthreads();
    float inv = sInv;
    int idx = blockIdx.x * 256 + threadIdx.x;
    int bh = idx >> 16, r = idx & 65535, i = r >> 8, j = r & 255;
    Z[idx]  = tf32r(A2[(bh << 16) + (j << 8) + i] * inv);
    ZT[idx] = tf32r(A2[idx] * inv);
}

// ---------------- depthwise conv(k=33) + add + concat heads (+tf32 round) ----------
__global__ __launch_bounds__(256) void convcat_kernel(
    const float* __restrict__ V, const float* __restrict__ OH,
    const float* __restrict__ ker, float* __restrict__ CAT)
{
    int b = blockIdx.z, h = blockIdx.y, n0 = blockIdx.x * 64;
    int bh = b * H_ + h;
    __shared__ float sV[96][64];
    __shared__ float kw[33];
    int t = threadIdx.x;
    if (t < 33) kw[t] = ker[h * 33 + t];
    const float* Vb = V + (long long)bh * N_ * DH_;
    for (int idx = t; idx < 96 * 16; idx += 256) {
        int r = idx >> 4;
        int c4 = (idx & 15) * 4;
        int n = n0 - 16 + r;
        float4 val = make_float4(0.f, 0.f, 0.f, 0.f);
        if (n >= 0 && n < N_) val = *(const float4*)(Vb + (long long)n * DH_ + c4);
        *(float4*)&sV[r][c4] = val;
    }
    __syncthreads();
    int d = t & 63, nl0 = t >> 6;
#pragma unroll
    for (int ii = 0; ii < 16; ii++) {
        int nl = nl0 + ii * 4;
        float acc = 0.f;
#pragma unroll
        for (int tt = 0; tt < 33; tt++) acc = fmaf(sV[nl + tt][d], kw[tt], acc);
        int n = n0 + nl;
        float o = OH[((long long)bh * N_ + n) * DH_ + d] + acc;
        CAT[((long long)(b * N_ + n)) * 512 + h * 64 + d] = tf32r(o);
    }
}

// ---------------- host ----------------
extern "C" void kernel_launch(void* const* d_in, const int* in_sizes, int n_in,
                              void* d_out, int out_size)
{
    const float* x     = (const float*)d_in[0];
    const float* wqkv  = (const float*)d_in[1];
    const float* wout  = (const float*)d_in[2];
    const float* bout  = (const float*)d_in[3];
    const float* rker  = (const float*)d_in[4];
    float* out = (float*)d_out;

    cudaFuncSetAttribute(gemm_mma, cudaFuncAttributeMaxDynamicSharedMemorySize, DYN_SMEM);
    cudaFuncSetAttribute(gemm_mma_qkv, cudaFuncAttributeMaxDynamicSharedMemorySize, DYN_SMEM);
    cudaFuncSetAttribute(gemm_mma64, cudaFuncAttributeMaxDynamicSharedMemorySize, DYN_SMEM64);
    cudaFuncSetAttribute(fused_attn_mma, cudaFuncAttributeMaxDynamicSharedMemorySize, DYN_ATTN);

    float *pQ, *pK, *pV, *pQL, *pKL, *pA2, *pZ, *pZT, *pZ2, *pZ2T, *pX;
    float *pT1, *pT2, *pA3V, *pW, *pOH, *pCAT, *pWqkvT, *pWoutT, *pPart, *pMS, *pCM;
    cudaGetSymbolAddress((void**)&pQ,  gQ);
    cudaGetSymbolAddress((void**)&pK,  gK);
    cudaGetSymbolAddress((void**)&pV,  gV);
    cudaGetSymbolAddress((void**)&pQL, gQL);
    cudaGetSymbolAddress((void**)&pKL, gKL);
    cudaGetSymbolAddress((void**)&pA2, gA2);
    cudaGetSymbolAddress((void**)&pZ,  gZ);
    cudaGetSymbolAddress((void**)&pZT, gZT);
    cudaGetSymbolAddress((void**)&pZ2, gZ2);
    cudaGetSymbolAddress((void**)&pZ2T, gZ2T);
    cudaGetSymbolAddress((void**)&pX,  gX);
    cudaGetSymbolAddress((void**)&pT1, gT1);
    cudaGetSymbolAddress((void**)&pT2, gT2);
    cudaGetSymbolAddress((void**)&pA3V, gA3V);
    cudaGetSymbolAddress((void**)&pW,  gW);
    cudaGetSymbolAddress((void**)&pOH, gOH);
    cudaGetSymbolAddress((void**)&pCAT, gCAT);
    cudaGetSymbolAddress((void**)&pWqkvT, gWqkvT);
    cudaGetSymbolAddress((void**)&pWoutT, gWoutT);
    cudaGetSymbolAddress((void**)&pPart, gPart);
    cudaGetSymbolAddress((void**)&pMS, gMS);
    cudaGetSymbolAddress((void**)&pCM, gColMax);

    const long long MM = (long long)M_ * M_;
    const long long MD = (long long)M_ * DH_;
    const long long ND = (long long)N_ * DH_;

    // 0) transpose+round both weight matrices in one launch
    transpose_kernel<<<48 * 16 + 16 * 16, dim3(32, 8)>>>(wqkv, wout, pWqkvT, pWoutT);
    // 1) qkv GEMM with scatter epilogue
    gemm_mma_qkv<<<dim3(12, 256), 256, DYN_SMEM>>>(x, pWqkvT, pQ, pK, pV);
    // 2) landmarks (Q and K in one launch)
    landmark_kernel<<<dim3(M_, BH_, 2), DH_>>>(pQ, pK, pQL, pKL);
    // 3) attn2 = softmax(QL @ KL^T)
    gemm_mma64<<<dim3(4, 4, BH_), 128, DYN_SMEM64>>>(pQL, pKL, pA2, nullptr,
                                                     64, 256, 0, MD, MD, MM, 0,
                                                     1.f, 0.f, 0.f, 0.f, 0);
    softmax_rows256<<<1024, 256>>>(pA2);
    // 4) pinv init (no atomics)
    colmax_kernel<<<BH_, 256>>>(pA2, pCM);
    zinit_kernel<<<8192, 256>>>(pA2, pCM, pZ, pZT);
    // 5) Newton-Schulz iterations
    float *zin = pZ, *zinT = pZT, *zout = pZ2, *zoutT = pZ2T;
    for (int it = 0; it < 6; it++) {
        gemm_mma64<<<dim3(4, 4, BH_), 128, DYN_SMEM64>>>(pA2, zinT, pX, pT1,
                                                         256, 256, 256, MM, MM, MM, MM,
                                                         1.f, 0.f, -1.f, 7.f, 1);
        gemm_mma64<<<dim3(4, 4, BH_), 128, DYN_SMEM64>>>(pX, pT1, nullptr, pT2,
                                                         256, 256, 256, MM, MM, MM, MM,
                                                         0.f, 0.f, -1.f, 15.f, 1);
        gemm_mma64<<<dim3(4, 4, BH_), 128, DYN_SMEM64>>>(pX, pT2, nullptr, pT1,
                                                         256, 256, 256, MM, MM, MM, MM,
                                                         0.f, 0.f, -1.f, 13.f, 1);
        gemm_mma64<<<dim3(4, 4, BH_), 128, DYN_SMEM64>>>(zin, pT1, zout, zoutT,
                                                         256, 256, 256, MM, MM, MM, MM,
                                                         0.25f, 0.f, 0.25f, 0.f, 1);
        float* t;
        t = zin; zin = zout; zout = t;
        t = zinT; zinT = zoutT; zoutT = t;
    }
    // 6) A3V = softmax(QL @ K^T) @ V: split flash + combine
    fused_attn_mma<<<dim3(32, BH_), 256, DYN_ATTN>>>(pQL, pK, pV, pPart,
                                                     4, 16, MD, ND, MD, pMS);
    combine_kernel<<<1024, 256>>>(pPart, pMS, pA3V);
    // 7) W = Zfinal @ A3V (FFMA NN, outputs rounded)
    gemm_nn<<<dim3(2, 1, BH_), 256>>>(zin, pA3V, pW, 256, 64, 256, MM, MD, MD);
    // 8) OH = softmax(Q @ KL^T) @ W (non-split flash)
    fused_attn_mma<<<dim3(128, BH_), 256, DYN_ATTN>>>(pQ, pKL, pW, pOH,
                                                      128, 4, ND, MD, ND, nullptr);
    // 9) conv + concat
    convcat_kernel<<<dim3(128, H_, B_), 256>>>(pV, pOH, rker, pCAT);
    // 10) out = CAT @ wout + bout
    gemm_mma<<<dim3(4, 256), 256, DYN_SMEM>>>(pCAT, pWoutT, out, nullptr, bout,
                                              512, 512, 0, 0, 0, 0, 0,
                                              1.f, 0.f, 0.f, 0.f, 0);
}